// round 2
// baseline (speedup 1.0000x reference)
#include <cuda_runtime.h>

#define HH 512
#define WW 512
#define BATCH 32
#define CHN 3

#define TX 64
#define TY 32
#define NTHREADS 512

// tile extents
#define RAW_H (TY + 6)   // 38 rows: by-3 .. by+TY+2
#define RAW_W (TX + 6)   // 70 cols: bx-3 .. bx+TX+2
#define RAW_WP 72
#define HB_H  (TY + 6)   // 38 rows (same rows as raw)
#define HB_W  (TX + 2)   // 66 cols: bx-1 .. bx+TX
#define HB_WP 68
#define BL_H  (TY + 2)   // 34 rows: by-1 .. by+TY
#define BL_W  (TX + 2)   // 66 cols: bx-1 .. bx+TX
#define BL_WP 68

__device__ unsigned int g_max_bits;

__global__ void reset_kernel() { g_max_bits = 0u; }

__global__ __launch_bounds__(NTHREADS) void edge_pass1(
    const float* __restrict__ img,
    const float* __restrict__ gauss,
    const float* __restrict__ sobel,
    float* __restrict__ out)
{
    __shared__ float raw[RAW_H][RAW_WP];
    __shared__ float hb [HB_H ][HB_WP ];
    __shared__ float bl [BL_H ][BL_WP ];
    __shared__ float wmax[16];

    const int tid = threadIdx.x;
    const int bx = blockIdx.x * TX;
    const int by = blockIdx.y * TY;
    const int b  = blockIdx.z;

    float g[5];
#pragma unroll
    for (int i = 0; i < 5; i++) g[i] = __ldg(&gauss[i]);
    float sb[3][3];
#pragma unroll
    for (int r = 0; r < 3; r++)
#pragma unroll
        for (int s = 0; s < 3; s++) sb[r][s] = __ldg(&sobel[r * 3 + s]);

    const int tx = tid & 63;
    const int ty = tid >> 6;          // 0..7; each thread owns 4 rows (stride 8)

    float acc[4] = {0.f, 0.f, 0.f, 0.f};

    for (int c = 0; c < CHN; c++) {
        // ---- stage raw tile, zero-padded at image borders ----
        const float* src = img + ((size_t)(b * CHN + c) * HH) * WW;
        for (int i = tid; i < RAW_H * RAW_W; i += NTHREADS) {
            int ry = i / RAW_W;
            int rx = i - ry * RAW_W;
            int gy = by + ry - 3;
            int gx = bx + rx - 3;
            float v = 0.f;
            if ((unsigned)gy < HH && (unsigned)gx < WW)
                v = __ldg(&src[(size_t)gy * WW + gx]);
            raw[ry][rx] = v;
        }
        __syncthreads();

        // ---- horizontal gaussian: hb[ry][rx], col = bx-1+rx ----
        // raw col offset: (bx-1+rx-2) - (bx-3) = rx + k, k=0..4
        for (int i = tid; i < HB_H * HB_W; i += NTHREADS) {
            int ry = i / HB_W;
            int rx = i - ry * HB_W;
            float s = 0.f;
#pragma unroll
            for (int k = 0; k < 5; k++)
                s = fmaf(raw[ry][rx + k], g[k], s);
            hb[ry][rx] = s;
        }
        __syncthreads();

        // ---- vertical gaussian + zero mask outside image ----
        // bl[vy][rx]: row = by-1+vy, col = bx-1+rx
        for (int i = tid; i < BL_H * BL_W; i += NTHREADS) {
            int vy = i / BL_W;
            int rx = i - vy * BL_W;
            int gy = by + vy - 1;
            int gx = bx + rx - 1;
            float s = 0.f;
            if ((unsigned)gy < HH && (unsigned)gx < WW) {
#pragma unroll
                for (int k = 0; k < 5; k++)
                    s = fmaf(hb[vy + k][rx], g[k], s);
            }
            bl[vy][rx] = s;   // blur cropped to image, zero outside (SAME pad for sobel)
        }
        __syncthreads();

        // ---- 3x3 sobel (gx) and its transpose (gy), accumulate mag^2 ----
#pragma unroll
        for (int k = 0; k < 4; k++) {
            int vy = ty + k * 8 + 1;       // blur-tile row of output pixel
            int cx = tx + 1;
            float gxv = 0.f, gyv = 0.f;
#pragma unroll
            for (int r = 0; r < 3; r++) {
#pragma unroll
                for (int s = 0; s < 3; s++) {
                    float v = bl[vy - 1 + r][cx - 1 + s];
                    gxv = fmaf(v, sb[r][s], gxv);   // sobel
                    gyv = fmaf(v, sb[s][r], gyv);   // sobel.T
                }
            }
            acc[k] = fmaf(gxv, gxv, fmaf(gyv, gyv, acc[k]));
        }
        __syncthreads();   // protect raw/hb/bl before next channel overwrites
    }

    // ---- magnitude, store, block max ----
    float m = 0.f;
#pragma unroll
    for (int k = 0; k < 4; k++) {
        float mg = sqrtf(acc[k]);
        int oy = by + ty + k * 8;
        out[((size_t)b * HH + oy) * WW + bx + tx] = mg;
        m = fmaxf(m, mg);
    }
#pragma unroll
    for (int o = 16; o; o >>= 1)
        m = fmaxf(m, __shfl_xor_sync(0xffffffffu, m, o));
    if ((tid & 31) == 0) wmax[tid >> 5] = m;
    __syncthreads();
    if (tid < 16) {
        m = wmax[tid];
#pragma unroll
        for (int o = 8; o; o >>= 1)
            m = fmaxf(m, __shfl_xor_sync(0xffffu, m, o));
        if (tid == 0)
            atomicMax(&g_max_bits, __float_as_uint(m));
    }
}

__global__ __launch_bounds__(256) void normalize_kernel(float* __restrict__ out, int n4)
{
    const float inv = 1.0f / __uint_as_float(g_max_bits);
    float4* p = (float4*)out;
    for (int i = blockIdx.x * blockDim.x + threadIdx.x; i < n4;
         i += gridDim.x * blockDim.x) {
        float4 v = p[i];
        v.x *= inv; v.y *= inv; v.z *= inv; v.w *= inv;
        p[i] = v;
    }
}

extern "C" void kernel_launch(void* const* d_in, const int* in_sizes, int n_in,
                              void* d_out, int out_size)
{
    const float* img   = (const float*)d_in[0];
    const float* gauss = (const float*)d_in[1];
    const float* sobel = (const float*)d_in[2];
    float* out = (float*)d_out;

    reset_kernel<<<1, 1>>>();

    dim3 grid(WW / TX, HH / TY, BATCH);   // (8, 16, 32)
    edge_pass1<<<grid, NTHREADS>>>(img, gauss, sobel, out);

    int n4 = out_size / 4;                // 2,097,152 float4
    normalize_kernel<<<8192, 256>>>(out, n4);
}